// round 8
// baseline (speedup 1.0000x reference)
#include <cuda_runtime.h>
#include <stdint.h>

// Problem constants (fixed by the reference)
#define BATCH 128
#define NN    512
#define NBINS 100
#define WPR   (NN / 32)   // 16 words per bitset row
#define RSTR  20          // padded row stride in words (80B, 16B-aligned)
#define NBLK  128         // persistent blocks (all co-resident: <= 148 SMs)

// Scratch (allocation-free: __device__ globals)
__device__ float    g_histf[2][BATCH][NBINS];   // histograms (exact small ints)
__device__ float    g_acc[3];                   // Kxx, Kyy, Kxy sums
__device__ unsigned g_sync = 0;                 // hist-done barrier counter
__device__ unsigned g_done = 0;                 // mmd completion ticket

// 32x32 bit-matrix transpose across a warp: out[l] bit k = in[k] bit l.
__device__ __forceinline__ uint32_t transpose32(uint32_t x, int lane) {
#pragma unroll
    for (int i = 16; i > 0; i >>= 1) {
        uint32_t m = (i == 16) ? 0xFFFF0000u : (i == 8) ? 0xFF00FF00u
                   : (i == 4)  ? 0xF0F0F0F0u : (i == 2) ? 0xCCCCCCCCu
                                             : 0xAAAAAAAAu;
        uint32_t y = __shfl_xor_sync(0xffffffffu, x, i);
        x = (lane & i) ? ((x & m) | ((y & m) >> i))
                       : ((x & ~m) | ((y & ~m) << i));
    }
    return x;
}

// ---------------------------------------------------------------------------
// ONE persistent kernel: 128 blocks, each processes 2 graphs (pack + mirror +
// triangles + histogram), then a device-wide counter barrier, then the same
// blocks compute the RBF-MMD tiles; last block out writes the scalar.
// ---------------------------------------------------------------------------
__global__ void __launch_bounds__(512) fused_kernel(
        const float* __restrict__ a1, const float* __restrict__ a2,
        float* __restrict__ out) {
    __shared__ uint4 rows4[NN][RSTR / 4];    // 40960 B
    __shared__ int   shist[NBINS];
    __shared__ float xs[16][NBINS + 1];      // mmd staging (stride 101)
    __shared__ float ys[16][NBINS + 1];
    __shared__ float red[8];

    int wid  = threadIdx.x >> 5;
    int lane = threadIdx.x & 31;

    if (blockIdx.x == 0 && threadIdx.x < 3) g_acc[threadIdx.x] = 0.0f;

#define PACK_PANEL(vv, rr, qq) {                                          \
    uint32_t bx = __ballot_sync(0xffffffffu, (vv).x != 0.0f);             \
    uint32_t by = __ballot_sync(0xffffffffu, (vv).y != 0.0f);             \
    uint32_t bz = __ballot_sync(0xffffffffu, (vv).z != 0.0f);             \
    uint32_t bw = __ballot_sync(0xffffffffu, (vv).w != 0.0f);             \
    if (lane == 0) rows4[rr][qq] = make_uint4(bx, by, bz, bw); }

    // ================= per-graph phase: 2 graphs per block =================
    for (int g = 0; g < 2; ++g) {
        int sb = blockIdx.x * 2 + g;   // 0..255
        int s  = sb >> 7;
        int b  = sb & (BATCH - 1);

        const float4* __restrict__ src =
            reinterpret_cast<const float4*>((s ? a2 : a1) + (size_t)b * NN * NN);

        // ---- Phase A: pack upper panels only, rows paired (t, 511-t) ----
        for (int t = wid; t < 256; t += 16) {
            int ra = t;
            int rb = 511 - t;
            const float4* pa = src + ra * (NN / 4);
            const float4* pb = src + rb * (NN / 4);
            int qa0 = ra >> 7;       // 0 or 1 (warp-uniform)
            int qb0 = rb >> 7;       // 3 or 2 (warp-uniform)

            float4 va0, va1, va2, va3, vb2, vb3;   // 5 loads in flight
            if (qa0 == 0) va0 = pa[0 * 32 + lane];
            va1 = pa[1 * 32 + lane];
            va2 = pa[2 * 32 + lane];
            va3 = pa[3 * 32 + lane];
            if (qb0 == 2) vb2 = pb[2 * 32 + lane];
            vb3 = pb[3 * 32 + lane];

            if (qa0 == 0) PACK_PANEL(va0, ra, 0);
            PACK_PANEL(va1, ra, 1);
            PACK_PANEL(va2, ra, 2);
            PACK_PANEL(va3, ra, 3);
            if (qb0 == 2) PACK_PANEL(vb2, rb, 2);
            PACK_PANEL(vb3, rb, 3);
        }
        if (threadIdx.x < NBINS) shist[threadIdx.x] = 0;
        __syncthreads();

        // ---- Phase M: mirror lower panels (R,Q), Q<R, from upper (Q,R) ----
        if (wid < 6) {
            const int RT[6] = {1, 2, 2, 3, 3, 3};
            const int QT[6] = {0, 0, 1, 0, 1, 2};
            int R = RT[wid], Q = QT[wid];
            uint4 u0 = rows4[128 * Q + 4 * lane + 0][R];
            uint4 u1 = rows4[128 * Q + 4 * lane + 1][R];
            uint4 u2 = rows4[128 * Q + 4 * lane + 2][R];
            uint4 u3 = rows4[128 * Q + 4 * lane + 3][R];
            u0.x = transpose32(u0.x, lane); u0.y = transpose32(u0.y, lane);
            u0.z = transpose32(u0.z, lane); u0.w = transpose32(u0.w, lane);
            u1.x = transpose32(u1.x, lane); u1.y = transpose32(u1.y, lane);
            u1.z = transpose32(u1.z, lane); u1.w = transpose32(u1.w, lane);
            u2.x = transpose32(u2.x, lane); u2.y = transpose32(u2.y, lane);
            u2.z = transpose32(u2.z, lane); u2.w = transpose32(u2.w, lane);
            u3.x = transpose32(u3.x, lane); u3.y = transpose32(u3.y, lane);
            u3.z = transpose32(u3.z, lane); u3.w = transpose32(u3.w, lane);
            rows4[128 * R + 4 * lane + 0][Q] = make_uint4(u0.x, u1.x, u2.x, u3.x);
            rows4[128 * R + 4 * lane + 1][Q] = make_uint4(u0.y, u1.y, u2.y, u3.y);
            rows4[128 * R + 4 * lane + 2][Q] = make_uint4(u0.z, u1.z, u2.z, u3.z);
            rows4[128 * R + 4 * lane + 3][Q] = make_uint4(u0.w, u1.w, u2.w, u3.w);
        }
        __syncthreads();

        // ---- Phase B: triangles. One thread per node. ----
        int i = threadIdx.x;
        uint32_t my[WPR];
        int deg = 0;
        {
            const uint4* r4 = rows4[i];
#pragma unroll
            for (int k = 0; k < 4; ++k) {
                uint4 v = r4[k];
                my[4*k]   = v.x; my[4*k+1] = v.y; my[4*k+2] = v.z; my[4*k+3] = v.w;
                deg += __popc(v.x) + __popc(v.y) + __popc(v.z) + __popc(v.w);
            }
        }

        int tri = 0;
#pragma unroll
        for (int w = 0; w < WPR; ++w) {
            uint32_t m = my[w];
            int base = (w >> 2) * 128 + (w & 3);   // permutation inverse
            while (m) {
                int l = __ffs(m) - 1;
                m &= m - 1;
                int j = base + 4 * l;
                const uint4* rj = rows4[j];
                int c = 0;
#pragma unroll
                for (int k = 0; k < 4; ++k) {
                    uint4 v = rj[k];               // LDS.128
                    c += __popc(my[4*k]   & v.x) + __popc(my[4*k+1] & v.y)
                       + __popc(my[4*k+2] & v.z) + __popc(my[4*k+3] & v.w);
                }
                tri += c;
            }
        }

        // ---- Phase C: bin (IEEE-exact vs JAX fp32) + histogram ----
        int bin = 0;
        if (deg >= 2) {
            float denom = (float)deg * (float)(deg - 1);
            float c  = __fdiv_rn((float)tri, denom);
            float cb = __fmul_rn(c, (float)NBINS);
            bin = (int)cb;
            bin = bin < 0 ? 0 : (bin > NBINS - 1 ? NBINS - 1 : bin);
        }
        atomicAdd(&shist[bin], 1);
        __syncthreads();

        if (threadIdx.x < NBINS)
            g_histf[s][b][threadIdx.x] = (float)shist[threadIdx.x];
        __syncthreads();
    }

    // ============ device-wide barrier (all 128 blocks co-resident) ============
    if (threadIdx.x == 0) {
        __threadfence();
        atomicAdd(&g_sync, 1u);
        while (*(volatile unsigned*)&g_sync < (unsigned)NBLK) { }
    }
    __syncthreads();
    __threadfence();

    // ================= mmd phase: 16x16 tiles, t = bid, bid+128 =============
    int t = threadIdx.x;
    int ti = t >> 4;
    int tj = t & 15;

    for (int tile = blockIdx.x; tile < 192; tile += NBLK) {
        int m  = tile >> 6;          // 0: (h1,h1)  1: (h2,h2)  2: (h1,h2)
        int r  = tile & 63;
        int i0 = (r >> 3) << 4;
        int j0 = (r & 7) << 4;

        const float* __restrict__ hx0 = &g_histf[(m == 1) ? 1 : 0][0][0];
        const float* __restrict__ hy0 = &g_histf[(m == 0) ? 0 : 1][0][0];

        for (int e = t; e < 16 * NBINS; e += 512) {
            int rr = e / NBINS, k = e % NBINS;
            xs[rr][k] = hx0[(i0 + rr) * NBINS + k];
            ys[rr][k] = hy0[(j0 + rr) * NBINS + k];
        }
        __syncthreads();

        float kv = 0.0f;
        if (t < 256) {
            float d2 = 0.0f;
#pragma unroll 4
            for (int k = 0; k < NBINS; ++k) {
                float d = xs[ti][k] - ys[tj][k];
                d2 = fmaf(d, d, d2);
            }
            kv = expf(-0.5f * d2);
        }
#pragma unroll
        for (int o = 16; o; o >>= 1)
            kv += __shfl_down_sync(0xffffffffu, kv, o);
        if ((t & 31) == 0) red[t >> 5] = (t < 256) ? kv : 0.0f;
        __syncthreads();
        if (t < 32) {
            float v = (t < 8) ? red[t] : 0.0f;
#pragma unroll
            for (int o = 4; o; o >>= 1)
                v += __shfl_down_sync(0xffffffffu, v, o);
            if (t == 0) atomicAdd(&g_acc[m], v);
        }
        __syncthreads();
    }

    // last-block-out finalize + counter reset (replay-deterministic)
    if (t == 0) {
        __threadfence();
        unsigned tk = atomicAdd(&g_done, 1u);
        if (tk == (unsigned)(NBLK - 1)) {
            __threadfence();
            const float inv = 1.0f / (128.0f * 128.0f);
            out[0] = (g_acc[0] + g_acc[1] - 2.0f * g_acc[2]) * inv;
            g_done = 0;
            g_sync = 0;
        }
    }
}

// ---------------------------------------------------------------------------
extern "C" void kernel_launch(void* const* d_in, const int* in_sizes, int n_in,
                              void* d_out, int out_size) {
    const float* a1 = (const float*)d_in[0];
    const float* a2 = (const float*)d_in[1];
    fused_kernel<<<NBLK, 512>>>(a1, a2, (float*)d_out);
}

// round 9
// speedup vs baseline: 1.1312x; 1.1312x over previous
#include <cuda_runtime.h>
#include <stdint.h>

// Problem constants (fixed by the reference)
#define BATCH 128
#define NN    512
#define NBINS 100
#define WPR   (NN / 32)   // 16 words per bitset row
#define RSTR  20          // padded row stride in words (80B, 16B-aligned)
#define NBLK  256         // persistent blocks; 2/SM co-resident (<= 296 cap)

// Scratch (allocation-free: __device__ globals)
__device__ float    g_histf[2][BATCH][NBINS];   // histograms (exact small ints)
__device__ float    g_acc[3];                   // Kxx, Kyy, Kxy sums
__device__ unsigned g_sync = 0;                 // hist-done barrier counter
__device__ unsigned g_done = 0;                 // completion ticket

// 32x32 bit-matrix transpose across a warp: out[l] bit k = in[k] bit l.
__device__ __forceinline__ uint32_t transpose32(uint32_t x, int lane) {
#pragma unroll
    for (int i = 16; i > 0; i >>= 1) {
        uint32_t m = (i == 16) ? 0xFFFF0000u : (i == 8) ? 0xFF00FF00u
                   : (i == 4)  ? 0xF0F0F0F0u : (i == 2) ? 0xCCCCCCCCu
                                             : 0xAAAAAAAAu;
        uint32_t y = __shfl_xor_sync(0xffffffffu, x, i);
        x = (lane & i) ? ((x & m) | ((y & m) >> i))
                       : ((x & ~m) | ((y & ~m) << i));
    }
    return x;
}

// ---------------------------------------------------------------------------
// ONE persistent kernel: 256 blocks (2/SM -> 32 warps/SM for DRAM latency
// hiding), each packs+counts ONE graph, device-wide counter barrier, then
// blocks 0..191 each compute one 16x16 RBF tile; last block out finalizes.
// mmd staging memory is UNIONed over the (dead) bitset buffer to keep
// smem/block at ~41.4KB so 2 blocks/SM are guaranteed co-resident.
// ---------------------------------------------------------------------------
struct MmdStage {
    float xs[16][NBINS + 1];
    float ys[16][NBINS + 1];
    float red[8];
};

__global__ void __launch_bounds__(512) fused_kernel(
        const float* __restrict__ a1, const float* __restrict__ a2,
        float* __restrict__ out) {
    __shared__ __align__(16) union {
        uint4 rows4[NN][RSTR / 4];           // 40960 B (graph phase)
        MmdStage mm;                          // 12960 B (mmd phase)
    } u;
    __shared__ int shist[NBINS];

    int wid  = threadIdx.x >> 5;
    int lane = threadIdx.x & 31;

    if (blockIdx.x == 0 && threadIdx.x < 3) g_acc[threadIdx.x] = 0.0f;

#define PACK_PANEL(vv, rr, qq) {                                          \
    uint32_t bx = __ballot_sync(0xffffffffu, (vv).x != 0.0f);             \
    uint32_t by = __ballot_sync(0xffffffffu, (vv).y != 0.0f);             \
    uint32_t bz = __ballot_sync(0xffffffffu, (vv).z != 0.0f);             \
    uint32_t bw = __ballot_sync(0xffffffffu, (vv).w != 0.0f);             \
    if (lane == 0) u.rows4[rr][qq] = make_uint4(bx, by, bz, bw); }

    // ================= graph phase: ONE graph per block =================
    {
        int sb = blockIdx.x;           // 0..255
        int s  = sb >> 7;
        int b  = sb & (BATCH - 1);

        const float4* __restrict__ src =
            reinterpret_cast<const float4*>((s ? a2 : a1) + (size_t)b * NN * NN);

        // ---- Phase A: pack upper panels only, rows paired (t, 511-t) ----
        for (int t = wid; t < 256; t += 16) {
            int ra = t;
            int rb = 511 - t;
            const float4* pa = src + ra * (NN / 4);
            const float4* pb = src + rb * (NN / 4);
            int qa0 = ra >> 7;         // 0 or 1 (warp-uniform)
            int qb0 = rb >> 7;         // 3 or 2 (warp-uniform)

            float4 va0, va1, va2, va3, vb2, vb3;   // 5-6 loads in flight
            if (qa0 == 0) va0 = pa[0 * 32 + lane];
            va1 = pa[1 * 32 + lane];
            va2 = pa[2 * 32 + lane];
            va3 = pa[3 * 32 + lane];
            if (qb0 == 2) vb2 = pb[2 * 32 + lane];
            vb3 = pb[3 * 32 + lane];

            if (qa0 == 0) PACK_PANEL(va0, ra, 0);
            PACK_PANEL(va1, ra, 1);
            PACK_PANEL(va2, ra, 2);
            PACK_PANEL(va3, ra, 3);
            if (qb0 == 2) PACK_PANEL(vb2, rb, 2);
            PACK_PANEL(vb3, rb, 3);
        }
        if (threadIdx.x < NBINS) shist[threadIdx.x] = 0;
        __syncthreads();

        // ---- Phase M: mirror lower panels (R,Q), Q<R, from upper (Q,R) ----
        if (wid < 6) {
            const int RT[6] = {1, 2, 2, 3, 3, 3};
            const int QT[6] = {0, 0, 1, 0, 1, 2};
            int R = RT[wid], Q = QT[wid];
            uint4 u0 = u.rows4[128 * Q + 4 * lane + 0][R];
            uint4 u1 = u.rows4[128 * Q + 4 * lane + 1][R];
            uint4 u2 = u.rows4[128 * Q + 4 * lane + 2][R];
            uint4 u3 = u.rows4[128 * Q + 4 * lane + 3][R];
            u0.x = transpose32(u0.x, lane); u0.y = transpose32(u0.y, lane);
            u0.z = transpose32(u0.z, lane); u0.w = transpose32(u0.w, lane);
            u1.x = transpose32(u1.x, lane); u1.y = transpose32(u1.y, lane);
            u1.z = transpose32(u1.z, lane); u1.w = transpose32(u1.w, lane);
            u2.x = transpose32(u2.x, lane); u2.y = transpose32(u2.y, lane);
            u2.z = transpose32(u2.z, lane); u2.w = transpose32(u2.w, lane);
            u3.x = transpose32(u3.x, lane); u3.y = transpose32(u3.y, lane);
            u3.z = transpose32(u3.z, lane); u3.w = transpose32(u3.w, lane);
            u.rows4[128 * R + 4 * lane + 0][Q] = make_uint4(u0.x, u1.x, u2.x, u3.x);
            u.rows4[128 * R + 4 * lane + 1][Q] = make_uint4(u0.y, u1.y, u2.y, u3.y);
            u.rows4[128 * R + 4 * lane + 2][Q] = make_uint4(u0.z, u1.z, u2.z, u3.z);
            u.rows4[128 * R + 4 * lane + 3][Q] = make_uint4(u0.w, u1.w, u2.w, u3.w);
        }
        __syncthreads();

        // ---- Phase B: triangles. One thread per node. ----
        int i = threadIdx.x;
        uint32_t my[WPR];
        int deg = 0;
        {
            const uint4* r4 = u.rows4[i];
#pragma unroll
            for (int k = 0; k < 4; ++k) {
                uint4 v = r4[k];
                my[4*k]   = v.x; my[4*k+1] = v.y; my[4*k+2] = v.z; my[4*k+3] = v.w;
                deg += __popc(v.x) + __popc(v.y) + __popc(v.z) + __popc(v.w);
            }
        }

        int tri = 0;
#pragma unroll
        for (int w = 0; w < WPR; ++w) {
            uint32_t m = my[w];
            int base = (w >> 2) * 128 + (w & 3);   // permutation inverse
            while (m) {
                int l = __ffs(m) - 1;
                m &= m - 1;
                int j = base + 4 * l;
                const uint4* rj = u.rows4[j];
                int c = 0;
#pragma unroll
                for (int k = 0; k < 4; ++k) {
                    uint4 v = rj[k];               // LDS.128
                    c += __popc(my[4*k]   & v.x) + __popc(my[4*k+1] & v.y)
                       + __popc(my[4*k+2] & v.z) + __popc(my[4*k+3] & v.w);
                }
                tri += c;
            }
        }

        // ---- Phase C: bin (IEEE-exact vs JAX fp32) + histogram ----
        int bin = 0;
        if (deg >= 2) {
            float denom = (float)deg * (float)(deg - 1);
            float c  = __fdiv_rn((float)tri, denom);
            float cb = __fmul_rn(c, (float)NBINS);
            bin = (int)cb;
            bin = bin < 0 ? 0 : (bin > NBINS - 1 ? NBINS - 1 : bin);
        }
        atomicAdd(&shist[bin], 1);
        __syncthreads();

        if (threadIdx.x < NBINS)
            g_histf[s][b][threadIdx.x] = (float)shist[threadIdx.x];
        __syncthreads();   // shist/rows4 dead after this point
    }

    // ============ device-wide barrier (all 256 blocks co-resident) ============
    if (threadIdx.x == 0) {
        __threadfence();
        atomicAdd(&g_sync, 1u);
        while (*(volatile unsigned*)&g_sync < (unsigned)NBLK) { }
    }
    __syncthreads();
    __threadfence();

    // ================= mmd phase: blocks 0..191 do one tile each ============
    int t = threadIdx.x;
    if (blockIdx.x < 192) {
        int tile = blockIdx.x;
        int m  = tile >> 6;          // 0: (h1,h1)  1: (h2,h2)  2: (h1,h2)
        int r  = tile & 63;
        int i0 = (r >> 3) << 4;
        int j0 = (r & 7) << 4;

        const float* __restrict__ hx0 = &g_histf[(m == 1) ? 1 : 0][0][0];
        const float* __restrict__ hy0 = &g_histf[(m == 0) ? 0 : 1][0][0];

        for (int e = t; e < 16 * NBINS; e += 512) {
            int rr = e / NBINS, k = e % NBINS;
            u.mm.xs[rr][k] = hx0[(i0 + rr) * NBINS + k];
            u.mm.ys[rr][k] = hy0[(j0 + rr) * NBINS + k];
        }
        __syncthreads();

        float kv = 0.0f;
        if (t < 256) {
            int ti = t >> 4, tj = t & 15;
            float d2 = 0.0f;
#pragma unroll 4
            for (int k = 0; k < NBINS; ++k) {
                float d = u.mm.xs[ti][k] - u.mm.ys[tj][k];
                d2 = fmaf(d, d, d2);
            }
            kv = expf(-0.5f * d2);
        }
#pragma unroll
        for (int o = 16; o; o >>= 1)
            kv += __shfl_down_sync(0xffffffffu, kv, o);
        if ((t & 31) == 0) u.mm.red[t >> 5] = (t < 256) ? kv : 0.0f;
        __syncthreads();
        if (t < 32) {
            float v = (t < 8) ? u.mm.red[t] : 0.0f;
#pragma unroll
            for (int o = 4; o; o >>= 1)
                v += __shfl_down_sync(0xffffffffu, v, o);
            if (t == 0) atomicAdd(&g_acc[m], v);
        }
        __syncthreads();
    }

    // last-block-out finalize + counter reset (replay-deterministic)
    if (t == 0) {
        __threadfence();
        unsigned tk = atomicAdd(&g_done, 1u);
        if (tk == (unsigned)(NBLK - 1)) {
            __threadfence();
            const float inv = 1.0f / (128.0f * 128.0f);
            out[0] = (g_acc[0] + g_acc[1] - 2.0f * g_acc[2]) * inv;
            g_done = 0;
            g_sync = 0;
        }
    }
}

// ---------------------------------------------------------------------------
extern "C" void kernel_launch(void* const* d_in, const int* in_sizes, int n_in,
                              void* d_out, int out_size) {
    const float* a1 = (const float*)d_in[0];
    const float* a2 = (const float*)d_in[1];
    fused_kernel<<<NBLK, 512>>>(a1, a2, (float*)d_out);
}

// round 10
// speedup vs baseline: 1.3861x; 1.2253x over previous
#include <cuda_runtime.h>
#include <stdint.h>

// Problem constants (fixed by the reference)
#define BATCH 128
#define NN    512
#define NBINS 100
#define WPR   (NN / 32)   // 16 words per bitset row
#define RSTR  20          // padded row stride in words (80B, 16B-aligned)
#define NBLK  256         // persistent blocks; 2/SM co-resident (enforced)

// Scratch (allocation-free: __device__ globals)
__device__ float    g_histf[2][BATCH][NBINS];   // histograms (exact small ints)
__device__ float    g_acc[3];                   // Kxx, Kyy, Kxy sums
__device__ unsigned g_sync = 0;                 // hist-done barrier counter
__device__ unsigned g_done = 0;                 // completion ticket

// 32x32 bit-matrix transpose across a warp: out[l] bit k = in[k] bit l.
__device__ __forceinline__ uint32_t transpose32(uint32_t x, int lane) {
#pragma unroll
    for (int i = 16; i > 0; i >>= 1) {
        uint32_t m = (i == 16) ? 0xFFFF0000u : (i == 8) ? 0xFF00FF00u
                   : (i == 4)  ? 0xF0F0F0F0u : (i == 2) ? 0xCCCCCCCCu
                                             : 0xAAAAAAAAu;
        uint32_t y = __shfl_xor_sync(0xffffffffu, x, i);
        x = (lane & i) ? ((x & m) | ((y & m) >> i))
                       : ((x & ~m) | ((y & ~m) << i));
    }
    return x;
}

struct MmdStage {
    float xs[16][NBINS + 1];
    float ys[16][NBINS + 1];
    float red[8];
};

// ---------------------------------------------------------------------------
// ONE persistent kernel: 256 blocks (2/SM guaranteed by launch_bounds),
// each packs+counts ONE graph, device-wide counter barrier, then blocks
// 0..191 each compute one 16x16 RBF tile; last block out finalizes.
//  A: symmetric read (62.5% of bytes), 2-stage software pipeline: exactly 5
//     panel-loads per row-pair (va0 XOR vb2, warp-uniform), 10 in flight.
//  M: mirror sub-diagonal panels via warp 32x32 bit transposes.
//  B: triangles with a UNIFORM-trip next-set-bit iterator (n < deg), not
//     per-word while loops -> warp iterations ~ max-deg, not sum-of-maxes.
// ---------------------------------------------------------------------------
__global__ void __launch_bounds__(512, 2) fused_kernel(
        const float* __restrict__ a1, const float* __restrict__ a2,
        float* __restrict__ out) {
    __shared__ __align__(16) union {
        uint4 rows4[NN][RSTR / 4];           // 40960 B (graph phase)
        MmdStage mm;                          // 12960 B (mmd phase)
    } u;
    __shared__ int shist[NBINS];

    int wid  = threadIdx.x >> 5;
    int lane = threadIdx.x & 31;

    if (blockIdx.x == 0 && threadIdx.x < 3) g_acc[threadIdx.x] = 0.0f;

#define PACK_PANEL(vv, rr, qq) {                                          \
    uint32_t bx = __ballot_sync(0xffffffffu, (vv).x != 0.0f);             \
    uint32_t by = __ballot_sync(0xffffffffu, (vv).y != 0.0f);             \
    uint32_t bz = __ballot_sync(0xffffffffu, (vv).z != 0.0f);             \
    uint32_t bw = __ballot_sync(0xffffffffu, (vv).w != 0.0f);             \
    if (lane == 0) u.rows4[rr][qq] = make_uint4(bx, by, bz, bw); }

#define LOAD5(tt, v0, v1, v2, v3, v4) {                                   \
    const float4* pa = src + (tt) * (NN / 4);                             \
    const float4* pb = src + (511 - (tt)) * (NN / 4);                     \
    (v0) = ((tt) < 128) ? pa[lane] : pb[64 + lane];                       \
    (v1) = pa[32 + lane];                                                 \
    (v2) = pa[64 + lane];                                                 \
    (v3) = pa[96 + lane];                                                 \
    (v4) = pb[96 + lane]; }

#define PACK5(tt, v0, v1, v2, v3, v4) {                                   \
    int ra = (tt), rb = 511 - (tt);                                       \
    if ((tt) < 128) { PACK_PANEL(v0, ra, 0) }                             \
    else            { PACK_PANEL(v0, rb, 2) }                             \
    PACK_PANEL(v1, ra, 1)                                                 \
    PACK_PANEL(v2, ra, 2)                                                 \
    PACK_PANEL(v3, ra, 3)                                                 \
    PACK_PANEL(v4, rb, 3) }

    // ================= graph phase: ONE graph per block =================
    {
        int sb = blockIdx.x;           // 0..255
        int s  = sb >> 7;
        int b  = sb & (BATCH - 1);

        const float4* __restrict__ src =
            reinterpret_cast<const float4*>((s ? a2 : a1) + (size_t)b * NN * NN);

        // ---- Phase A: pipelined pack; rows paired (t, 511-t) ----
        {
            float4 x0, x1, x2, x3, x4, y0, y1, y2, y3, y4;
            LOAD5(wid, x0, x1, x2, x3, x4);
#pragma unroll 1
            for (int t = wid; t < 256; t += 32) {     // 8 trips, 2 pairs each
                LOAD5(t + 16, y0, y1, y2, y3, y4);
                PACK5(t, x0, x1, x2, x3, x4);
                if (t + 32 < 256) LOAD5(t + 32, x0, x1, x2, x3, x4);
                PACK5(t + 16, y0, y1, y2, y3, y4);
            }
        }
        if (threadIdx.x < NBINS) shist[threadIdx.x] = 0;
        __syncthreads();

        // ---- Phase M: mirror lower panels (R,Q), Q<R, from upper (Q,R) ----
        if (wid < 6) {
            const int RT[6] = {1, 2, 2, 3, 3, 3};
            const int QT[6] = {0, 0, 1, 0, 1, 2};
            int R = RT[wid], Q = QT[wid];
            uint4 u0 = u.rows4[128 * Q + 4 * lane + 0][R];
            uint4 u1 = u.rows4[128 * Q + 4 * lane + 1][R];
            uint4 u2 = u.rows4[128 * Q + 4 * lane + 2][R];
            uint4 u3 = u.rows4[128 * Q + 4 * lane + 3][R];
            u0.x = transpose32(u0.x, lane); u0.y = transpose32(u0.y, lane);
            u0.z = transpose32(u0.z, lane); u0.w = transpose32(u0.w, lane);
            u1.x = transpose32(u1.x, lane); u1.y = transpose32(u1.y, lane);
            u1.z = transpose32(u1.z, lane); u1.w = transpose32(u1.w, lane);
            u2.x = transpose32(u2.x, lane); u2.y = transpose32(u2.y, lane);
            u2.z = transpose32(u2.z, lane); u2.w = transpose32(u2.w, lane);
            u3.x = transpose32(u3.x, lane); u3.y = transpose32(u3.y, lane);
            u3.z = transpose32(u3.z, lane); u3.w = transpose32(u3.w, lane);
            u.rows4[128 * R + 4 * lane + 0][Q] = make_uint4(u0.x, u1.x, u2.x, u3.x);
            u.rows4[128 * R + 4 * lane + 1][Q] = make_uint4(u0.y, u1.y, u2.y, u3.y);
            u.rows4[128 * R + 4 * lane + 2][Q] = make_uint4(u0.z, u1.z, u2.z, u3.z);
            u.rows4[128 * R + 4 * lane + 3][Q] = make_uint4(u0.w, u1.w, u2.w, u3.w);
        }
        __syncthreads();

        // ---- Phase B: triangles. One thread per node, uniform trips. ----
        int i = threadIdx.x;
        uint32_t my[WPR];
        int deg = 0;
        {
            const uint4* r4 = u.rows4[i];
#pragma unroll
            for (int k = 0; k < 4; ++k) {
                uint4 v = r4[k];
                my[4*k]   = v.x; my[4*k+1] = v.y; my[4*k+2] = v.z; my[4*k+3] = v.w;
                deg += __popc(v.x) + __popc(v.y) + __popc(v.z) + __popc(v.w);
            }
        }

        int tri = 0;
        {
            int w = 0;
            uint32_t m = my[0];
            for (int n = 0; n < deg; ++n) {       // warp trips = max(deg)
                while (m == 0) m = my[++w];       // cheap word skip
                int l = __ffs(m) - 1;
                m &= m - 1;
                int j = (w >> 2) * 128 + 4 * l + (w & 3);   // perm inverse
                const uint4* rj = u.rows4[j];
                int c = 0;
#pragma unroll
                for (int k = 0; k < 4; ++k) {
                    uint4 v = rj[k];              // LDS.128
                    c += __popc(my[4*k]   & v.x) + __popc(my[4*k+1] & v.y)
                       + __popc(my[4*k+2] & v.z) + __popc(my[4*k+3] & v.w);
                }
                tri += c;
            }
        }

        // ---- Phase C: bin (IEEE-exact vs JAX fp32) + histogram ----
        int bin = 0;
        if (deg >= 2) {
            float denom = (float)deg * (float)(deg - 1);
            float c  = __fdiv_rn((float)tri, denom);
            float cb = __fmul_rn(c, (float)NBINS);
            bin = (int)cb;
            bin = bin < 0 ? 0 : (bin > NBINS - 1 ? NBINS - 1 : bin);
        }
        atomicAdd(&shist[bin], 1);
        __syncthreads();

        if (threadIdx.x < NBINS)
            g_histf[s][b][threadIdx.x] = (float)shist[threadIdx.x];
        __syncthreads();   // shist/rows4 dead after this point
    }

    // ============ device-wide barrier (all 256 blocks co-resident) ============
    if (threadIdx.x == 0) {
        __threadfence();
        atomicAdd(&g_sync, 1u);
        while (*(volatile unsigned*)&g_sync < (unsigned)NBLK) { }
    }
    __syncthreads();
    __threadfence();

    // ================= mmd phase: blocks 0..191 do one tile each ============
    int t = threadIdx.x;
    if (blockIdx.x < 192) {
        int tile = blockIdx.x;
        int m  = tile >> 6;          // 0: (h1,h1)  1: (h2,h2)  2: (h1,h2)
        int r  = tile & 63;
        int i0 = (r >> 3) << 4;
        int j0 = (r & 7) << 4;

        const float* __restrict__ hx0 = &g_histf[(m == 1) ? 1 : 0][0][0];
        const float* __restrict__ hy0 = &g_histf[(m == 0) ? 0 : 1][0][0];

        for (int e = t; e < 16 * NBINS; e += 512) {
            int rr = e / NBINS, k = e % NBINS;
            u.mm.xs[rr][k] = hx0[(i0 + rr) * NBINS + k];
            u.mm.ys[rr][k] = hy0[(j0 + rr) * NBINS + k];
        }
        __syncthreads();

        float kv = 0.0f;
        if (t < 256) {
            int ti = t >> 4, tj = t & 15;
            float d2 = 0.0f;
#pragma unroll 4
            for (int k = 0; k < NBINS; ++k) {
                float d = u.mm.xs[ti][k] - u.mm.ys[tj][k];
                d2 = fmaf(d, d, d2);
            }
            kv = expf(-0.5f * d2);
        }
#pragma unroll
        for (int o = 16; o; o >>= 1)
            kv += __shfl_down_sync(0xffffffffu, kv, o);
        if ((t & 31) == 0) u.mm.red[t >> 5] = (t < 256) ? kv : 0.0f;
        __syncthreads();
        if (t < 32) {
            float v = (t < 8) ? u.mm.red[t] : 0.0f;
#pragma unroll
            for (int o = 4; o; o >>= 1)
                v += __shfl_down_sync(0xffffffffu, v, o);
            if (t == 0) atomicAdd(&g_acc[m], v);
        }
        __syncthreads();
    }

    // last-block-out finalize + counter reset (replay-deterministic)
    if (t == 0) {
        __threadfence();
        unsigned tk = atomicAdd(&g_done, 1u);
        if (tk == (unsigned)(NBLK - 1)) {
            __threadfence();
            const float inv = 1.0f / (128.0f * 128.0f);
            out[0] = (g_acc[0] + g_acc[1] - 2.0f * g_acc[2]) * inv;
            g_done = 0;
            g_sync = 0;
        }
    }
}

// ---------------------------------------------------------------------------
extern "C" void kernel_launch(void* const* d_in, const int* in_sizes, int n_in,
                              void* d_out, int out_size) {
    const float* a1 = (const float*)d_in[0];
    const float* a2 = (const float*)d_in[1];
    fused_kernel<<<NBLK, 512>>>(a1, a2, (float*)d_out);
}

// round 11
// speedup vs baseline: 1.7797x; 1.2840x over previous
#include <cuda_runtime.h>
#include <stdint.h>

// Problem constants (fixed by the reference)
#define BATCH 128
#define NN    512
#define NBINS 100
#define WPR   (NN / 32)   // 16 words per bitset row
#define RSTR  20          // padded row stride in words (80B, 16B-aligned)
#define NBLK  256         // persistent blocks; 2/SM co-resident
#define NCHUNK 16         // 16 chunks x 8 row-pairs = 256 pairs
#define SEGS  40          // 512B segments per chunk (8 pairs x 5 panels)

// Scratch (allocation-free: __device__ globals)
__device__ float    g_histf[2][BATCH][NBINS];
__device__ float    g_acc[3];
__device__ unsigned g_sync = 0;
__device__ unsigned g_done = 0;

struct MmdStage {
    float xs[16][NBINS + 1];
    float ys[16][NBINS + 1];
    float red[8];
};

struct Smem {
    uint4 rows4[NN][RSTR / 4];                         // 40960 B bitset
    union { float4 stage[2][SEGS * 32]; MmdStage mm; } s2;  // 40960 B
};

// 32x32 bit-matrix transpose across a warp.
__device__ __forceinline__ uint32_t transpose32(uint32_t x, int lane) {
#pragma unroll
    for (int i = 16; i > 0; i >>= 1) {
        uint32_t m = (i == 16) ? 0xFFFF0000u : (i == 8) ? 0xFF00FF00u
                   : (i == 4)  ? 0xF0F0F0F0u : (i == 2) ? 0xCCCCCCCCu
                                             : 0xAAAAAAAAu;
        uint32_t y = __shfl_xor_sync(0xffffffffu, x, i);
        x = (lane & i) ? ((x & m) | ((y & m) >> i))
                       : ((x & ~m) | ((y & ~m) << i));
    }
    return x;
}

// segment -> (row, panel q). Chunk c covers row-pairs (c*8 .. c*8+7), each
// pair t needs panels: [0]=(t,0) or (511-t,2), [1..3]=(t,1..3), [4]=(511-t,3).
__device__ __forceinline__ void seg_to_rowq(int s, int c, int& row, int& q) {
    int pl    = s / 5;
    int panel = s - 5 * pl;
    int t = c * 8 + pl;
    if (panel == 0)      { if (t < 128) { row = t; q = 0; } else { row = 511 - t; q = 2; } }
    else if (panel <= 3) { row = t;       q = panel; }
    else                 { row = 511 - t; q = 3; }
}

// ---------------------------------------------------------------------------
// ONE persistent kernel, 256 blocks (2/SM). Phase A is a cp.async double-
// buffered chunk pipeline (20KB chunks, 2 in flight -> 80KB/SM outstanding,
// no register pressure) feeding a ballot-pack from warm smem.
// Then mirror transposes, triangle counts, histograms, device barrier, RBF.
// ---------------------------------------------------------------------------
__global__ void __launch_bounds__(512, 2) fused_kernel(
        const float* __restrict__ a1, const float* __restrict__ a2,
        float* __restrict__ out) {
    extern __shared__ __align__(16) char smem_raw[];
    Smem& U = *reinterpret_cast<Smem*>(smem_raw);
    __shared__ int shist[NBINS];

    int wid  = threadIdx.x >> 5;
    int lane = threadIdx.x & 31;

    if (blockIdx.x == 0 && threadIdx.x < 3) g_acc[threadIdx.x] = 0.0f;
    if (threadIdx.x < NBINS) shist[threadIdx.x] = 0;

    // ================= graph phase: ONE graph per block =================
    {
        int sb = blockIdx.x;
        int s  = sb >> 7;
        int b  = sb & (BATCH - 1);
        const char* __restrict__ base =
            reinterpret_cast<const char*>((s ? a2 : a1) + (size_t)b * NN * NN);

#define ISSUE_CHUNK(cc, buf) {                                             \
    for (int e = threadIdx.x; e < SEGS * 32; e += 512) {                   \
        int sg = e >> 5, x = e & 31;                                       \
        int row, q; seg_to_rowq(sg, (cc), row, q);                         \
        const char* g = base + row * 2048 + q * 512 + x * 16;              \
        uint32_t d = (uint32_t)__cvta_generic_to_shared(                   \
            &U.s2.stage[buf][e]);                                          \
        asm volatile("cp.async.cg.shared.global [%0], [%1], 16;"           \
                     :: "r"(d), "l"(g));                                   \
    }                                                                      \
    asm volatile("cp.async.commit_group;" ::: "memory"); }

#define PACK_CHUNK(cc, buf) {                                              \
    for (int sg = wid; sg < SEGS; sg += 16) {                              \
        int row, q; seg_to_rowq(sg, (cc), row, q);                         \
        float4 v = U.s2.stage[buf][sg * 32 + lane];                        \
        uint32_t bx = __ballot_sync(0xffffffffu, v.x != 0.0f);             \
        uint32_t by = __ballot_sync(0xffffffffu, v.y != 0.0f);             \
        uint32_t bz = __ballot_sync(0xffffffffu, v.z != 0.0f);             \
        uint32_t bw = __ballot_sync(0xffffffffu, v.w != 0.0f);             \
        if (lane == 0) U.rows4[row][q] = make_uint4(bx, by, bz, bw);       \
    } }

        // ---- Phase A: double-buffered cp.async pipeline ----
        ISSUE_CHUNK(0, 0);
        ISSUE_CHUNK(1, 1);
#pragma unroll 1
        for (int c = 0; c < NCHUNK; ++c) {
            if (c == NCHUNK - 1)
                asm volatile("cp.async.wait_group 0;" ::: "memory");
            else
                asm volatile("cp.async.wait_group 1;" ::: "memory");
            __syncthreads();                 // chunk c visible to all
            PACK_CHUNK(c, c & 1);
            __syncthreads();                 // buffer free before reuse
            if (c + 2 < NCHUNK) ISSUE_CHUNK(c + 2, c & 1);
        }

        // ---- Phase M: mirror lower panels (R,Q), Q<R, from upper (Q,R) ----
        if (wid < 6) {
            const int RT[6] = {1, 2, 2, 3, 3, 3};
            const int QT[6] = {0, 0, 1, 0, 1, 2};
            int R = RT[wid], Q = QT[wid];
            uint4 u0 = U.rows4[128 * Q + 4 * lane + 0][R];
            uint4 u1 = U.rows4[128 * Q + 4 * lane + 1][R];
            uint4 u2 = U.rows4[128 * Q + 4 * lane + 2][R];
            uint4 u3 = U.rows4[128 * Q + 4 * lane + 3][R];
            u0.x = transpose32(u0.x, lane); u0.y = transpose32(u0.y, lane);
            u0.z = transpose32(u0.z, lane); u0.w = transpose32(u0.w, lane);
            u1.x = transpose32(u1.x, lane); u1.y = transpose32(u1.y, lane);
            u1.z = transpose32(u1.z, lane); u1.w = transpose32(u1.w, lane);
            u2.x = transpose32(u2.x, lane); u2.y = transpose32(u2.y, lane);
            u2.z = transpose32(u2.z, lane); u2.w = transpose32(u2.w, lane);
            u3.x = transpose32(u3.x, lane); u3.y = transpose32(u3.y, lane);
            u3.z = transpose32(u3.z, lane); u3.w = transpose32(u3.w, lane);
            U.rows4[128 * R + 4 * lane + 0][Q] = make_uint4(u0.x, u1.x, u2.x, u3.x);
            U.rows4[128 * R + 4 * lane + 1][Q] = make_uint4(u0.y, u1.y, u2.y, u3.y);
            U.rows4[128 * R + 4 * lane + 2][Q] = make_uint4(u0.z, u1.z, u2.z, u3.z);
            U.rows4[128 * R + 4 * lane + 3][Q] = make_uint4(u0.w, u1.w, u2.w, u3.w);
        }
        __syncthreads();

        // ---- Phase B: triangles. One thread per node, uniform trips. ----
        int i = threadIdx.x;
        uint32_t my[WPR];
        int deg = 0;
        {
            const uint4* r4 = U.rows4[i];
#pragma unroll
            for (int k = 0; k < 4; ++k) {
                uint4 v = r4[k];
                my[4*k]   = v.x; my[4*k+1] = v.y; my[4*k+2] = v.z; my[4*k+3] = v.w;
                deg += __popc(v.x) + __popc(v.y) + __popc(v.z) + __popc(v.w);
            }
        }

        int tri = 0;
        {
            int w = 0;
            uint32_t m = my[0];
            for (int n = 0; n < deg; ++n) {
                while (m == 0) m = my[++w];
                int l = __ffs(m) - 1;
                m &= m - 1;
                int j = (w >> 2) * 128 + 4 * l + (w & 3);   // perm inverse
                const uint4* rj = U.rows4[j];
                int c = 0;
#pragma unroll
                for (int k = 0; k < 4; ++k) {
                    uint4 v = rj[k];                        // LDS.128
                    c += __popc(my[4*k]   & v.x) + __popc(my[4*k+1] & v.y)
                       + __popc(my[4*k+2] & v.z) + __popc(my[4*k+3] & v.w);
                }
                tri += c;
            }
        }

        // ---- Phase C: bin (IEEE-exact vs JAX fp32) + histogram ----
        int bin = 0;
        if (deg >= 2) {
            float denom = (float)deg * (float)(deg - 1);
            float c  = __fdiv_rn((float)tri, denom);
            float cb = __fmul_rn(c, (float)NBINS);
            bin = (int)cb;
            bin = bin < 0 ? 0 : (bin > NBINS - 1 ? NBINS - 1 : bin);
        }
        atomicAdd(&shist[bin], 1);
        __syncthreads();

        if (threadIdx.x < NBINS)
            g_histf[s][b][threadIdx.x] = (float)shist[threadIdx.x];
        __syncthreads();
    }

    // ============ device-wide barrier (all 256 blocks co-resident) ============
    if (threadIdx.x == 0) {
        __threadfence();
        atomicAdd(&g_sync, 1u);
        while (*(volatile unsigned*)&g_sync < (unsigned)NBLK) { }
    }
    __syncthreads();
    __threadfence();

    // ================= mmd phase: blocks 0..191 do one tile each ============
    int t = threadIdx.x;
    if (blockIdx.x < 192) {
        int tile = blockIdx.x;
        int m  = tile >> 6;
        int r  = tile & 63;
        int i0 = (r >> 3) << 4;
        int j0 = (r & 7) << 4;

        const float* __restrict__ hx0 = &g_histf[(m == 1) ? 1 : 0][0][0];
        const float* __restrict__ hy0 = &g_histf[(m == 0) ? 0 : 1][0][0];

        for (int e = t; e < 16 * NBINS; e += 512) {
            int rr = e / NBINS, k = e % NBINS;
            U.s2.mm.xs[rr][k] = hx0[(i0 + rr) * NBINS + k];
            U.s2.mm.ys[rr][k] = hy0[(j0 + rr) * NBINS + k];
        }
        __syncthreads();

        float kv = 0.0f;
        if (t < 256) {
            int ti = t >> 4, tj = t & 15;
            float d2 = 0.0f;
#pragma unroll 4
            for (int k = 0; k < NBINS; ++k) {
                float d = U.s2.mm.xs[ti][k] - U.s2.mm.ys[tj][k];
                d2 = fmaf(d, d, d2);
            }
            kv = expf(-0.5f * d2);
        }
#pragma unroll
        for (int o = 16; o; o >>= 1)
            kv += __shfl_down_sync(0xffffffffu, kv, o);
        if ((t & 31) == 0) U.s2.mm.red[t >> 5] = (t < 256) ? kv : 0.0f;
        __syncthreads();
        if (t < 32) {
            float v = (t < 8) ? U.s2.mm.red[t] : 0.0f;
#pragma unroll
            for (int o = 4; o; o >>= 1)
                v += __shfl_down_sync(0xffffffffu, v, o);
            if (t == 0) atomicAdd(&g_acc[m], v);
        }
        __syncthreads();
    }

    // last-block-out finalize + counter reset (replay-deterministic)
    if (t == 0) {
        __threadfence();
        unsigned tk = atomicAdd(&g_done, 1u);
        if (tk == (unsigned)(NBLK - 1)) {
            __threadfence();
            const float inv = 1.0f / (128.0f * 128.0f);
            out[0] = (g_acc[0] + g_acc[1] - 2.0f * g_acc[2]) * inv;
            g_done = 0;
            g_sync = 0;
        }
    }
}

// ---------------------------------------------------------------------------
extern "C" void kernel_launch(void* const* d_in, const int* in_sizes, int n_in,
                              void* d_out, int out_size) {
    const float* a1 = (const float*)d_in[0];
    const float* a2 = (const float*)d_in[1];

    cudaFuncSetAttribute(fused_kernel,
                         cudaFuncAttributeMaxDynamicSharedMemorySize,
                         (int)sizeof(Smem));
    fused_kernel<<<NBLK, 512, sizeof(Smem)>>>(a1, a2, (float*)d_out);
}